// round 6
// baseline (speedup 1.0000x reference)
#include <cuda_runtime.h>
#include <cuda_bf16.h>
#include <math.h>

typedef unsigned long long u64;

// ---- f32x2 packed-math helpers (Blackwell FFMA2, only reachable via PTX) ----
__device__ __forceinline__ u64 splat2(float a) {
    u64 r; asm("mov.b64 %0,{%1,%1};" : "=l"(r) : "f"(a)); return r;
}
__device__ __forceinline__ void fma2(u64& d, u64 a, u64 b) {
    asm("fma.rn.f32x2 %0,%1,%2,%0;" : "+l"(d) : "l"(a), "l"(b));
}
__device__ __forceinline__ float2 unpk2(u64 v) {
    float2 f; asm("mov.b64 {%0,%1},%2;" : "=f"(f.x), "=f"(f.y) : "l"(v)); return f;
}

// ---------------- static scratch (device globals: allowed; no cudaMalloc) ----
__device__ float g_wmix[113246208];   // max: conv4 128*256*384*9 ; reused as FC split-K partials
__device__ float g_actA[24900000];    // max: conv1 out 128*64*55*55
__device__ float g_actB[6100000];     // max: pool1 out 128*64*27*27
__device__ float g_pool[128 * 384];
__device__ float g_route[128 * 8];
__device__ float g_bmix[128 * 384];

// ---------------- global average pool (per (b,c) block reduce) ---------------
__global__ void avgpool_k(const float* __restrict__ in, float* __restrict__ out, int HW) {
    __shared__ float sm[256];
    int bc = blockIdx.x;
    const float* p = in + (size_t)bc * HW;
    float s = 0.f;
    for (int i = threadIdx.x; i < HW; i += 256) s += p[i];
    sm[threadIdx.x] = s;
    __syncthreads();
    for (int o = 128; o > 0; o >>= 1) {
        if (threadIdx.x < o) sm[threadIdx.x] += sm[threadIdx.x + o];
        __syncthreads();
    }
    if (threadIdx.x == 0) out[bc] = sm[0] / (float)HW;
}

// ---------------- routing: r[b,k] = sigmoid(pooled[b,:]·rw[:,k] + rb[k]) -----
__global__ void route_k(const float* __restrict__ pooled, const float* __restrict__ rw,
                        const float* __restrict__ rb, float* __restrict__ r, int CIN) {
    int b = blockIdx.x;
    int k = threadIdx.x;   // blockDim = 8
    float s = rb[k];
    const float* pb = pooled + b * CIN;
    for (int c = 0; c < CIN; c++) s += pb[c] * rw[c * 8 + k];
    r[b * 8 + k] = 1.f / (1.f + expf(-s));
}

// ---------------- weight mixing: wmix[b,e] = sum_k r[b,k] * w[k,e] -----------
__global__ __launch_bounds__(256) void mixw_k(const float* __restrict__ r,
                                              const float* __restrict__ w,
                                              float* __restrict__ wmix, int E) {
    __shared__ float rs[128 * 8];
    int tid = threadIdx.x;
    for (int i = tid; i < 1024; i += 256) rs[i] = r[i];
    __syncthreads();
    int e = blockIdx.x * 256 + tid;
    if (e >= E) return;
    float wr[8];
#pragma unroll
    for (int k = 0; k < 8; k++) wr[k] = w[(size_t)k * E + e];
    for (int b = 0; b < 128; b++) {
        float s = 0.f;
#pragma unroll
        for (int k = 0; k < 8; k++) s += rs[b * 8 + k] * wr[k];
        wmix[(size_t)b * E + e] = s;
    }
}

// ---------------- bias mixing: bmix[b,c] = sum_k r[b,k] * bias[k,c] ----------
__global__ void mixb_k(const float* __restrict__ r, const float* __restrict__ bias,
                       float* __restrict__ bmix, int COUT) {
    int b = blockIdx.x;
    for (int c = threadIdx.x; c < COUT; c += blockDim.x) {
        float s = 0.f;
#pragma unroll
        for (int k = 0; k < 8; k++) s += r[b * 8 + k] * bias[k * COUT + c];
        bmix[b * COUT + c] = s;
    }
}

// ---------------- per-sample implicit-GEMM conv + bias + ReLU ----------------
// GEMM per sample b: C[Cout,P] = Wmix_b[Cout,KTOT] x Im2col_b[KTOT,P]
// 64 threads, 64x64 tile, BK=16, 8x8 microtile on packed f32x2, double-buffered.
template <int CIN, int COUT, int KS, int STRIDE, int PAD, int HIN, int WIN,
          int HOUT, int WOUT, bool RELU>
__global__ __launch_bounds__(64) void conv_ps(const float* __restrict__ in,
                                              const float* __restrict__ wmix,
                                              const float* __restrict__ bmix,
                                              float* __restrict__ out) {
    constexpr int KTOT = CIN * KS * KS;
    constexpr int P = HOUT * WOUT;
    __shared__ __align__(16) float As[2][16][68];
    __shared__ __align__(16) float Bs[2][16][68];

    int tid = threadIdx.x;
    int tx = tid & 7, ty = tid >> 3;            // microtile coords (8x8)
    int p0 = blockIdx.x * 64;
    int m0 = blockIdx.y * 64;
    int b = blockIdx.z;

    const float* wB = wmix + ((size_t)b * COUT + m0) * KTOT;
    const float* inB = in + (size_t)b * CIN * HIN * WIN;

    // Per-thread fixed output pixel for the B tile (n == tid)
    int p = p0 + tid;
    bool pok = p < P;
    int oy = p / WOUT, ox = p - oy * WOUT;
    int iy0 = oy * STRIDE - PAD;
    int ix0 = ox * STRIDE - PAD;
    // Per-thread fixed A lane
    int ka = tid & 15;                           // k within BK
    int ma = tid >> 4;                           // m base (rows ma + 4t)

    u64 acc[8][4];
#pragma unroll
    for (int i = 0; i < 8; i++)
#pragma unroll
        for (int j = 0; j < 4; j++) acc[i][j] = 0ull;

    float rA[16], rB[16];
    auto loadT = [&](int k0) {
        bool kaok = (k0 + ka) < KTOT;
#pragma unroll
        for (int t = 0; t < 16; t++) {
            int m = ma + t * 4;
            rA[t] = kaok ? wB[(size_t)m * KTOT + k0 + ka] : 0.f;
        }
        // incremental (cin,kh,kw) decomposition of kg = k0 + t (warp-uniform;
        // start via const-divide, then carry-propagate — no per-t div/mod)
        int cin = k0 / (KS * KS);
        int rem = k0 - cin * (KS * KS);
        int kh = rem / KS, kw = rem - kh * KS;
#pragma unroll
        for (int t = 0; t < 16; t++) {
            int kg = k0 + t;
            float v = 0.f;
            if (kg < KTOT && pok) {
                int iy = iy0 + kh, ix = ix0 + kw;
                if (iy >= 0 && iy < HIN && ix >= 0 && ix < WIN)
                    v = inB[(cin * HIN + iy) * WIN + ix];
            }
            rB[t] = v;
            if (++kw == KS) { kw = 0; if (++kh == KS) { kh = 0; ++cin; } }
        }
    };
    auto storeT = [&](int buf) {
#pragma unroll
        for (int t = 0; t < 16; t++) {
            As[buf][ka][ma + t * 4] = rA[t];
            Bs[buf][t][tid] = rB[t];
        }
    };

    loadT(0);
    storeT(0);
    __syncthreads();

    int cur = 0;
    for (int k0 = 0; k0 < KTOT; k0 += 16) {
        bool nxt = (k0 + 16 < KTOT);
        if (nxt) loadT(k0 + 16);
#pragma unroll
        for (int kk = 0; kk < 16; kk++) {
            float4 a0 = *(const float4*)&As[cur][kk][ty * 8];
            float4 a1 = *(const float4*)&As[cur][kk][ty * 8 + 4];
            ulonglong2 bb0 = *(const ulonglong2*)&Bs[cur][kk][tx * 8];
            ulonglong2 bb1 = *(const ulonglong2*)&Bs[cur][kk][tx * 8 + 4];
            u64 b2[4] = {bb0.x, bb0.y, bb1.x, bb1.y};
            float av[8] = {a0.x, a0.y, a0.z, a0.w, a1.x, a1.y, a1.z, a1.w};
#pragma unroll
            for (int i = 0; i < 8; i++) {
                u64 a2 = splat2(av[i]);
#pragma unroll
                for (int j = 0; j < 4; j++) fma2(acc[i][j], a2, b2[j]);
            }
        }
        if (nxt) {
            storeT(cur ^ 1);
            __syncthreads();
            cur ^= 1;
        }
    }

#pragma unroll
    for (int i = 0; i < 8; i++) {
        int m = m0 + ty * 8 + i;                 // COUT % 64 == 0 -> always valid
        float bias = bmix[b * COUT + m];
        float* orow = out + ((size_t)b * COUT + m) * P;
#pragma unroll
        for (int j = 0; j < 4; j++) {
            float2 v = unpk2(acc[i][j]);
            int pp = p0 + tx * 8 + 2 * j;
            float o0 = v.x + bias, o1 = v.y + bias;
            if (RELU) { o0 = fmaxf(o0, 0.f); o1 = fmaxf(o1, 0.f); }
            if (pp < P)     orow[pp] = o0;
            if (pp + 1 < P) orow[pp + 1] = o1;
        }
    }
}

// ---------------- maxpool 3x3 stride 2 VALID ---------------------------------
__global__ void maxpool_k(const float* __restrict__ in, float* __restrict__ out,
                          int C, int HIN, int WIN, int HOUT, int WOUT, int total) {
    int idx = blockIdx.x * blockDim.x + threadIdx.x;
    if (idx >= total) return;
    int ox = idx % WOUT;
    int t = idx / WOUT;
    int oy = t % HOUT; t /= HOUT;
    int c = t % C;
    int b = t / C;
    const float* p = in + (((size_t)b * C + c) * HIN + oy * 2) * WIN + ox * 2;
    float m = -INFINITY;
#pragma unroll
    for (int i = 0; i < 3; i++)
#pragma unroll
        for (int j = 0; j < 3; j++) m = fmaxf(m, p[i * WIN + j]);
    out[idx] = m;
}

// ---------------- FC split-K GEMM: part[z] = A[:, zKc:(z+1)Kc] * Bw[zKc:..] --
// 256 threads, 64x64xBK16 tile, 4x4 microtile on packed f32x2, double-buffered.
// blockIdx.z = split index; partials written WITHOUT bias/relu.
__global__ __launch_bounds__(256) void gemm_split(const float* __restrict__ A,
                                                  const float* __restrict__ Bw,
                                                  float* __restrict__ part,
                                                  int M, int N, int KdFull, int Kc) {
    __shared__ __align__(16) float As[2][16][68];
    __shared__ __align__(16) float Bs[2][16][68];
    int tid = threadIdx.x;
    int tx = tid & 15, ty = tid >> 4;
    int n0 = blockIdx.x * 64;
    int m0 = blockIdx.y * 64;
    int kbase = blockIdx.z * Kc;

    u64 acc[4][2];
#pragma unroll
    for (int i = 0; i < 4; i++) { acc[i][0] = 0ull; acc[i][1] = 0ull; }
    float rA[4], rB[4];

    auto loadA = [&](int k0, float ra[4]) {
#pragma unroll
        for (int i = 0; i < 4; i++) {
            int idx = tid + i * 256;
            int k = idx & 15, m = idx >> 4;
            int kg = k0 + k, mg = m0 + m;
            ra[i] = (kg < Kc && mg < M) ? A[(size_t)mg * KdFull + kbase + kg] : 0.f;
        }
    };
    auto loadB = [&](int k0, float rb_[4]) {
#pragma unroll
        for (int i = 0; i < 4; i++) {
            int idx = tid + i * 256;
            int k = idx >> 6, n = idx & 63;
            int kg = k0 + k, ng = n0 + n;
            rb_[i] = (kg < Kc && ng < N) ? Bw[(size_t)(kbase + kg) * N + ng] : 0.f;
        }
    };
    auto storeTile = [&](int buf, const float ra[4], const float rb_[4]) {
#pragma unroll
        for (int i = 0; i < 4; i++) {
            int idx = tid + i * 256;
            As[buf][idx & 15][idx >> 4] = ra[i];
            Bs[buf][idx >> 6][idx & 63] = rb_[i];
        }
    };

    loadA(0, rA);
    loadB(0, rB);
    storeTile(0, rA, rB);
    __syncthreads();

    int cur = 0;
    for (int k0 = 0; k0 < Kc; k0 += 16) {
        bool hasNext = (k0 + 16 < Kc);
        if (hasNext) {
            loadA(k0 + 16, rA);
            loadB(k0 + 16, rB);
        }
#pragma unroll
        for (int kk = 0; kk < 16; kk++) {
            float4 a4 = *(const float4*)&As[cur][kk][ty * 4];
            ulonglong2 bb = *(const ulonglong2*)&Bs[cur][kk][tx * 4];
            float av[4] = {a4.x, a4.y, a4.z, a4.w};
#pragma unroll
            for (int i = 0; i < 4; i++) {
                u64 a2 = splat2(av[i]);
                fma2(acc[i][0], a2, bb.x);
                fma2(acc[i][1], a2, bb.y);
            }
        }
        if (hasNext) {
            storeTile(cur ^ 1, rA, rB);
            __syncthreads();
            cur ^= 1;
        }
    }

    float* pz = part + (size_t)blockIdx.z * M * N;
#pragma unroll
    for (int i = 0; i < 4; i++) {
        int m = m0 + ty * 4 + i;
        if (m >= M) continue;
#pragma unroll
        for (int j = 0; j < 2; j++) {
            float2 v = unpk2(acc[i][j]);
            int n = n0 + tx * 4 + 2 * j;
            if (n < N)     pz[(size_t)m * N + n] = v.x;
            if (n + 1 < N) pz[(size_t)m * N + n + 1] = v.y;
        }
    }
}

// ---------------- split-K reduce + bias + optional ReLU ----------------------
template <int SPLITS, bool RELU>
__global__ void reduce_k(const float* __restrict__ part, const float* __restrict__ bias,
                         float* __restrict__ C, int M, int N) {
    int idx = blockIdx.x * blockDim.x + threadIdx.x;
    int total = M * N;
    if (idx >= total) return;
    int n = idx % N;
    float s = bias[n];
    size_t stride = (size_t)M * N;
#pragma unroll
    for (int z = 0; z < SPLITS; z++) s += part[z * stride + idx];
    if (RELU) s = fmaxf(s, 0.f);
    C[idx] = s;
}

// ---------------- host orchestration ----------------------------------------
extern "C" void kernel_launch(void* const* d_in, const int* in_sizes, int n_in,
                              void* d_out, int out_size) {
    const float* x = (const float*)d_in[0];
    const float *w[5], *bb[5], *rw[5], *rb[5];
    for (int l = 0; l < 5; l++) {
        w[l]  = (const float*)d_in[1 + 4 * l];
        bb[l] = (const float*)d_in[2 + 4 * l];
        rw[l] = (const float*)d_in[3 + 4 * l];
        rb[l] = (const float*)d_in[4 + 4 * l];
    }
    const float* fw1 = (const float*)d_in[21];
    const float* fb1 = (const float*)d_in[22];
    const float* fw2 = (const float*)d_in[23];
    const float* fb2 = (const float*)d_in[24];
    const float* fw3 = (const float*)d_in[25];
    const float* fb3 = (const float*)d_in[26];

    float *wmix, *actA, *actB, *pool, *r, *bmix;
    cudaGetSymbolAddress((void**)&wmix, g_wmix);
    cudaGetSymbolAddress((void**)&actA, g_actA);
    cudaGetSymbolAddress((void**)&actB, g_actB);
    cudaGetSymbolAddress((void**)&pool, g_pool);
    cudaGetSymbolAddress((void**)&r,    g_route);
    cudaGetSymbolAddress((void**)&bmix, g_bmix);

    auto pre = [&](const float* inp, int CIN, int HW, int l, int COUT, int E) {
        avgpool_k<<<128 * CIN, 256>>>(inp, pool, HW);
        route_k<<<128, 8>>>(pool, rw[l], rb[l], r, CIN);
        mixw_k<<<(E + 255) / 256, 256>>>(r, w[l], wmix, E);
        mixb_k<<<128, 256>>>(r, bb[l], bmix, COUT);
    };

    // ----- layer 1: 3->64, k=11, s=4, p=2; 224 -> 55 -> pool 27 -----
    pre(x, 3, 224 * 224, 0, 64, 64 * 3 * 121);
    conv_ps<3, 64, 11, 4, 2, 224, 224, 55, 55, true>
        <<<dim3(48, 1, 128), 64>>>(x, wmix, bmix, actA);
    maxpool_k<<<(128 * 64 * 27 * 27 + 255) / 256, 256>>>(actA, actB, 64, 55, 55, 27, 27,
                                                         128 * 64 * 27 * 27);

    // ----- layer 2: 64->192, k=5, p=2; 27 -> 27 -> pool 13 -----
    pre(actB, 64, 27 * 27, 1, 192, 192 * 64 * 25);
    conv_ps<64, 192, 5, 1, 2, 27, 27, 27, 27, true>
        <<<dim3(12, 3, 128), 64>>>(actB, wmix, bmix, actA);
    maxpool_k<<<(128 * 192 * 13 * 13 + 255) / 256, 256>>>(actA, actB, 192, 27, 27, 13, 13,
                                                          128 * 192 * 13 * 13);

    // ----- layer 3: 192->384, k=3, p=1; 13 -> 13 -----
    pre(actB, 192, 13 * 13, 2, 384, 384 * 192 * 9);
    conv_ps<192, 384, 3, 1, 1, 13, 13, 13, 13, true>
        <<<dim3(3, 6, 128), 64>>>(actB, wmix, bmix, actA);

    // ----- layer 4: 384->256, k=3, p=1 -----
    pre(actA, 384, 13 * 13, 3, 256, 256 * 384 * 9);
    conv_ps<384, 256, 3, 1, 1, 13, 13, 13, 13, true>
        <<<dim3(3, 4, 128), 64>>>(actA, wmix, bmix, actB);

    // ----- layer 5: 256->256, k=3, p=1; 13 -> 13 -> pool 6 -----
    pre(actB, 256, 13 * 13, 4, 256, 256 * 256 * 9);
    conv_ps<256, 256, 3, 1, 1, 13, 13, 13, 13, true>
        <<<dim3(3, 4, 128), 64>>>(actB, wmix, bmix, actA);
    maxpool_k<<<(128 * 256 * 6 * 6 + 255) / 256, 256>>>(actA, actB, 256, 13, 13, 6, 6,
                                                        128 * 256 * 6 * 6);

    // ----- FC head (split-K; partials in g_wmix, dead after conv phase) -----
    // FC1: 9216 -> 4096, split 8 (Kc = 1152)
    gemm_split<<<dim3(64, 2, 8), 256>>>(actB, fw1, wmix, 128, 4096, 9216, 1152);
    reduce_k<8, true><<<(128 * 4096 + 255) / 256, 256>>>(wmix, fb1, actA, 128, 4096);
    // FC2: 4096 -> 4096, split 4 (Kc = 1024)
    gemm_split<<<dim3(64, 2, 4), 256>>>(actA, fw2, wmix, 128, 4096, 4096, 1024);
    reduce_k<4, true><<<(128 * 4096 + 255) / 256, 256>>>(wmix, fb2, actB, 128, 4096);
    // FC3: 4096 -> 1000, split 8 (Kc = 512)
    gemm_split<<<dim3(16, 2, 8), 256>>>(actB, fw3, wmix, 128, 1000, 4096, 512);
    reduce_k<8, false><<<(128 * 1000 + 255) / 256, 256>>>(wmix, fb3, (float*)d_out, 128, 1000);
}